// round 16
// baseline (speedup 1.0000x reference)
#include <cuda_runtime.h>
#include <cuda_bf16.h>
#include <math.h>

// Problem constants
#define BB   512
#define LL   200
#define EE   256
#define HH   128
#define DD   256
#define TT   6
#define GATES 512
#define MROWS (BB*LL)   // 102400
#define VV   50000
#define KPS  21         // Whh k-pairs per team cached in smem
#define KPR  11         // k-pairs per team in registers (KPS+KPR = 32)
#define ROWS 7          // batch rows per LSTM block (74 groups x 2 dirs = 148 blocks)
#define NGRP 74
#define HPS  20         // sh_hp stride per kp (floats): 16B-aligned, ~conflict-free scatter

typedef unsigned long long u64;

// ---------------- scratch -----------------------------------------------------
__device__ float g_embW[(size_t)50048 * 1024];   // per-vocab gate preactivations
__device__ float g_h [(size_t)MROWS * DD];
__device__ float g_h1[(size_t)MROWS * DD];
__device__ float g_h2[(size_t)MROWS * DD];
__device__ float g_logits[(size_t)MROWS * TT];
__device__ float g_Wpack_f[HH * GATES];   // [kp][j][parity] interleaved k-pairs
__device__ float g_Wpack_b[HH * GATES];

// ---------------- f32x2 helpers ----------------------------------------------
__device__ __forceinline__ u64 pack2(float lo, float hi) {
    u64 r; asm("mov.b64 %0, {%1, %2};" : "=l"(r) : "f"(lo), "f"(hi)); return r;
}
__device__ __forceinline__ void unpack2(u64 v, float& lo, float& hi) {
    asm("mov.b64 {%0, %1}, %2;" : "=f"(lo), "=f"(hi) : "l"(v));
}
__device__ __forceinline__ void ffma2(u64& d, u64 a, u64 b) {
    asm("fma.rn.f32x2 %0, %1, %2, %0;" : "+l"(d) : "l"(a), "l"(b));
}

__device__ __forceinline__ float sigm(float x) { return 1.0f / (1.0f + expf(-x)); }
__device__ __forceinline__ float tanh_acc(float x) {
    float e = expf(2.0f * x);
    return 1.0f - 2.0f / (e + 1.0f);
}
__device__ __forceinline__ float leaky(float x) { return (x >= 0.0f) ? x : 0.01f * x; }

// ---------------- prep: k-pair-pack Whh only ---------------------------------
__global__ void prep_kernel(const float* __restrict__ Whh_f, const float* __restrict__ Whh_b) {
    int i = blockIdx.x * 256 + threadIdx.x;          // covers 65536
    int j = i >> 7, k = i & 127;                     // source Whh[j][k]
    int dst = (k >> 1) * 1024 + j * 2 + (k & 1);     // [kp][j][parity]
    g_Wpack_f[dst] = Whh_f[i];
    g_Wpack_b[dst] = Whh_b[i];
}

// ---------------- 128x64 fp32 GEMM, 3 blocks/SM, C = act(A @ Bw^T + bias) ----
// 8m x 4n per thread (16 u64 acc); 6 warps/SMSP for latency hiding.
template<int ACT>
__global__ void __launch_bounds__(256, 3) gemm64n(
    const float* __restrict__ A,
    const float* __restrict__ Bw, const float* __restrict__ bias,
    float* __restrict__ C, int N, int K, int Mmax)
{
    __shared__ float As[2][16][128];
    __shared__ float Bs[2][16][64];
    const int tid = threadIdx.x;
    const int mbase = blockIdx.y * 128;
    const int nbase = blockIdx.x * 64;

    // staging: A — thread=(row tid>>1, 8-k-half); B — thread=(row tid>>2, 4-k-quad)
    const int alr = tid >> 1;
    const int alc = (tid & 1) << 3;
    const int blr = tid >> 2;          // 0..63
    const int blc = (tid & 3) << 2;    // 0,4,8,12
    int arow_i = mbase + alr;
    if (arow_i > Mmax - 1) arow_i = Mmax - 1;
    const float* arow = A + (size_t)arow_i * K;
    const float* brow = Bw + (size_t)(nbase + blr) * K;

    const int m0 = (tid >> 4) << 2;    // 4*mg
    const int n0 = (tid & 15) << 2;    // 4*ng (covers 0..63)

    u64 acc[4][4];
#pragma unroll
    for (int i = 0; i < 4; i++)
#pragma unroll
        for (int j = 0; j < 4; j++) acc[i][j] = 0ull;

    float4 a0 = *(const float4*)(arow + alc);
    float4 a1 = *(const float4*)(arow + alc + 4);
    float4 b0 = *(const float4*)(brow + blc);
    As[0][alc + 0][alr] = a0.x; As[0][alc + 1][alr] = a0.y;
    As[0][alc + 2][alr] = a0.z; As[0][alc + 3][alr] = a0.w;
    As[0][alc + 4][alr] = a1.x; As[0][alc + 5][alr] = a1.y;
    As[0][alc + 6][alr] = a1.z; As[0][alc + 7][alr] = a1.w;
    Bs[0][blc + 0][blr] = b0.x; Bs[0][blc + 1][blr] = b0.y;
    Bs[0][blc + 2][blr] = b0.z; Bs[0][blc + 3][blr] = b0.w;
    __syncthreads();

    int buf = 0;
    for (int kt = 0; kt < K; kt += 16) {
        const bool more = (kt + 16) < K;
        if (more) {
            a0 = *(const float4*)(arow + kt + 16 + alc);
            a1 = *(const float4*)(arow + kt + 16 + alc + 4);
            b0 = *(const float4*)(brow + kt + 16 + blc);
        }
#pragma unroll
        for (int kk = 0; kk < 16; kk++) {
            ulonglong2 av0 = *(const ulonglong2*)(&As[buf][kk][m0]);
            ulonglong2 av1 = *(const ulonglong2*)(&As[buf][kk][64 + m0]);
            float4 bv = *(const float4*)(&Bs[buf][kk][n0]);
            u64 bp[4];
            bp[0] = pack2(bv.x, bv.x); bp[1] = pack2(bv.y, bv.y);
            bp[2] = pack2(bv.z, bv.z); bp[3] = pack2(bv.w, bv.w);
            u64 am[4] = {av0.x, av0.y, av1.x, av1.y};
#pragma unroll
            for (int mp = 0; mp < 4; mp++)
#pragma unroll
                for (int n = 0; n < 4; n++)
                    ffma2(acc[mp][n], am[mp], bp[n]);
        }
        if (more) {
            const int nb = buf ^ 1;
            As[nb][alc + 0][alr] = a0.x; As[nb][alc + 1][alr] = a0.y;
            As[nb][alc + 2][alr] = a0.z; As[nb][alc + 3][alr] = a0.w;
            As[nb][alc + 4][alr] = a1.x; As[nb][alc + 5][alr] = a1.y;
            As[nb][alc + 6][alr] = a1.z; As[nb][alc + 7][alr] = a1.w;
            Bs[nb][blc + 0][blr] = b0.x; Bs[nb][blc + 1][blr] = b0.y;
            Bs[nb][blc + 2][blr] = b0.z; Bs[nb][blc + 3][blr] = b0.w;
            __syncthreads();
            buf = nb;
        }
    }

    float bsv[4];
#pragma unroll
    for (int n = 0; n < 4; n++) bsv[n] = bias[nbase + n0 + n];

#pragma unroll
    for (int mp = 0; mp < 4; mp++) {
        float r0[4], r1[4];
#pragma unroll
        for (int n = 0; n < 4; n++) unpack2(acc[mp][n], r0[n], r1[n]);
        const int row0 = mbase + m0 + (mp & 1) * 2 + (mp >> 1) * 64;
        const size_t base0 = (size_t)row0 * N + nbase + n0;
        const size_t base1 = base0 + N;
        float4 v0, v1;
        float *p0 = (float*)&v0, *p1 = (float*)&v1;
#pragma unroll
        for (int n = 0; n < 4; n++) {
            float x0 = r0[n] + bsv[n];
            float x1 = r1[n] + bsv[n];
            if (ACT) { x0 = leaky(x0); x1 = leaky(x1); }
            p0[n] = x0; p1[n] = x1;
        }
        *(float4*)(&C[base0]) = v0;
        *(float4*)(&C[base1]) = v1;
    }
}

// ---------------- vocab GEMM: embW = emb @ [Wih_f;Wih_b]^T + (bih+bhh) -------
// R9-proven 128x128 tile; B rows < 512 from Wih_f, >= 512 from Wih_b.
__global__ void __launch_bounds__(256, 2) gemmvocab(
    const float* __restrict__ A,
    const float* __restrict__ Wf, const float* __restrict__ Wb,
    const float* __restrict__ bihf, const float* __restrict__ bhhf,
    const float* __restrict__ bihb, const float* __restrict__ bhhb,
    float* __restrict__ C)
{
    const int N = 1024, K = EE;
    __shared__ float As[2][16][128];
    __shared__ float Bs[2][16][128];
    const int tid = threadIdx.x;
    const int mbase = blockIdx.y * 128;
    const int nbase = blockIdx.x * 128;
    const int lr = tid >> 1;
    const int lc = (tid & 1) << 3;
    int arow_i = mbase + lr;
    if (arow_i > VV - 1) arow_i = VV - 1;
    const float* arow = A + (size_t)arow_i * K;
    const int bri = nbase + lr;
    const float* brow = (bri < 512) ? (Wf + (size_t)bri * K)
                                    : (Wb + (size_t)(bri - 512) * K);

    const int m0 = (tid >> 4) << 2;
    const int n0 = (tid & 15) << 2;

    u64 acc[4][8];
#pragma unroll
    for (int i = 0; i < 4; i++)
#pragma unroll
        for (int j = 0; j < 8; j++) acc[i][j] = 0ull;

    float4 a0 = *(const float4*)(arow + lc);
    float4 a1 = *(const float4*)(arow + lc + 4);
    float4 b0 = *(const float4*)(brow + lc);
    float4 b1 = *(const float4*)(brow + lc + 4);
    As[0][lc + 0][lr] = a0.x; As[0][lc + 1][lr] = a0.y;
    As[0][lc + 2][lr] = a0.z; As[0][lc + 3][lr] = a0.w;
    As[0][lc + 4][lr] = a1.x; As[0][lc + 5][lr] = a1.y;
    As[0][lc + 6][lr] = a1.z; As[0][lc + 7][lr] = a1.w;
    Bs[0][lc + 0][lr] = b0.x; Bs[0][lc + 1][lr] = b0.y;
    Bs[0][lc + 2][lr] = b0.z; Bs[0][lc + 3][lr] = b0.w;
    Bs[0][lc + 4][lr] = b1.x; Bs[0][lc + 5][lr] = b1.y;
    Bs[0][lc + 6][lr] = b1.z; Bs[0][lc + 7][lr] = b1.w;
    __syncthreads();

    int buf = 0;
    for (int kt = 0; kt < K; kt += 16) {
        const bool more = (kt + 16) < K;
        if (more) {
            a0 = *(const float4*)(arow + kt + 16 + lc);
            a1 = *(const float4*)(arow + kt + 16 + lc + 4);
            b0 = *(const float4*)(brow + kt + 16 + lc);
            b1 = *(const float4*)(brow + kt + 16 + lc + 4);
        }
#pragma unroll
        for (int kk = 0; kk < 16; kk++) {
            ulonglong2 av0 = *(const ulonglong2*)(&As[buf][kk][m0]);
            ulonglong2 av1 = *(const ulonglong2*)(&As[buf][kk][64 + m0]);
            float4 bv0 = *(const float4*)(&Bs[buf][kk][n0]);
            float4 bv1 = *(const float4*)(&Bs[buf][kk][64 + n0]);
            u64 bp[8];
            bp[0] = pack2(bv0.x, bv0.x); bp[1] = pack2(bv0.y, bv0.y);
            bp[2] = pack2(bv0.z, bv0.z); bp[3] = pack2(bv0.w, bv0.w);
            bp[4] = pack2(bv1.x, bv1.x); bp[5] = pack2(bv1.y, bv1.y);
            bp[6] = pack2(bv1.z, bv1.z); bp[7] = pack2(bv1.w, bv1.w);
            u64 am[4] = {av0.x, av0.y, av1.x, av1.y};
#pragma unroll
            for (int mp = 0; mp < 4; mp++)
#pragma unroll
                for (int n = 0; n < 8; n++)
                    ffma2(acc[mp][n], am[mp], bp[n]);
        }
        if (more) {
            const int nb = buf ^ 1;
            As[nb][lc + 0][lr] = a0.x; As[nb][lc + 1][lr] = a0.y;
            As[nb][lc + 2][lr] = a0.z; As[nb][lc + 3][lr] = a0.w;
            As[nb][lc + 4][lr] = a1.x; As[nb][lc + 5][lr] = a1.y;
            As[nb][lc + 6][lr] = a1.z; As[nb][lc + 7][lr] = a1.w;
            Bs[nb][lc + 0][lr] = b0.x; Bs[nb][lc + 1][lr] = b0.y;
            Bs[nb][lc + 2][lr] = b0.z; Bs[nb][lc + 3][lr] = b0.w;
            Bs[nb][lc + 4][lr] = b1.x; Bs[nb][lc + 5][lr] = b1.y;
            Bs[nb][lc + 6][lr] = b1.z; Bs[nb][lc + 7][lr] = b1.w;
            __syncthreads();
            buf = nb;
        }
    }

    float bsv[8];
#pragma unroll
    for (int n = 0; n < 8; n++) {
        const int col = nbase + ((n < 4) ? n0 + n : 64 + n0 + (n - 4));
        bsv[n] = (col < 512) ? (bihf[col] + bhhf[col])
                             : (bihb[col - 512] + bhhb[col - 512]);
    }

#pragma unroll
    for (int mp = 0; mp < 4; mp++) {
        float r0[8], r1[8];
#pragma unroll
        for (int n = 0; n < 8; n++) unpack2(acc[mp][n], r0[n], r1[n]);
        const int row0 = mbase + m0 + (mp & 1) * 2 + (mp >> 1) * 64;
        const size_t base0 = (size_t)row0 * N;
        const size_t base1 = base0 + N;
        float4 v00, v01, v10, v11;
        float *p00 = (float*)&v00, *p01 = (float*)&v01;
        float *p10 = (float*)&v10, *p11 = (float*)&v11;
#pragma unroll
        for (int n = 0; n < 4; n++) {
            p00[n] = r0[n] + bsv[n];     p01[n] = r0[4 + n] + bsv[4 + n];
            p10[n] = r1[n] + bsv[n];     p11[n] = r1[4 + n] + bsv[4 + n];
        }
        *(float4*)(&C[base0 + nbase + n0])      = v00;
        *(float4*)(&C[base0 + nbase + 64 + n0]) = v01;
        *(float4*)(&C[base1 + nbase + n0])      = v10;
        *(float4*)(&C[base1 + nbase + 64 + n0]) = v11;
    }
}

// ---------------- persistent BiLSTM: split-k, 7 rows/block, 148 blocks -------
#define MM14(ACA, ACB, W0, W1, HPTR)                                      \
    {                                                                     \
        const ulonglong2* hp_ = (const ulonglong2*)(HPTR);                \
        ulonglong2 hA = hp_[0], hB = hp_[1], hC = hp_[2];                 \
        u64 h6 = *(const u64*)(((const float*)(HPTR)) + 12);              \
        ffma2(ACA[0], hA.x, W0); ffma2(ACB[0], hA.x, W1);                 \
        ffma2(ACA[1], hA.y, W0); ffma2(ACB[1], hA.y, W1);                 \
        ffma2(ACA[2], hB.x, W0); ffma2(ACB[2], hB.x, W1);                 \
        ffma2(ACA[3], hB.y, W0); ffma2(ACB[3], hB.y, W1);                 \
        ffma2(ACA[4], hC.x, W0); ffma2(ACB[4], hC.x, W1);                 \
        ffma2(ACA[5], hC.y, W0); ffma2(ACB[5], hC.y, W1);                 \
        ffma2(ACA[6], h6,   W0); ffma2(ACB[6], h6,   W1);                 \
    }

__global__ void __launch_bounds__(512) lstm_kernel(
    const int* __restrict__ sentences,
    const float* __restrict__ xgv,
    const float* __restrict__ Wp_f, const float* __restrict__ Wp_b,
    float* __restrict__ hout)
{
    extern __shared__ float dyn[];
    float* sWp   = dyn;                           // [2 teams][KPS][512][2]
    float* sh_hp = dyn + 2 * KPS * 1024;          // [64 kp][HPS]
    float* sh_c  = sh_hp + 64 * HPS;              // [7][128]
    float* sh_g  = sh_c + ROWS * HH;              // [7][512] team0 partial + xg
    float* sh_gp = sh_g + ROWS * GATES;           // [7][512] team1 partial

    const int tid = threadIdx.x;
    const int team = tid >> 8;
    const int tt = tid & 255;
    const int c0 = tt, c1 = tt + 256;
    const int dir = blockIdx.x & 1;
    const int b0 = (blockIdx.x >> 1) * ROWS;
    const float* __restrict__ W = dir ? Wp_b : Wp_f;
    const u64* __restrict__ W64 = (const u64*)W;

    for (int i = tid; i < 2 * KPS * 1024; i += 512) {
        int slot = i >> 10, c = i & 1023;
        int m = slot / KPS, p = slot - m * KPS;
        sWp[i] = W[((m * 32 + p) << 10) + c];
    }
    u64 wr0[KPR], wr1[KPR];
#pragma unroll
    for (int q = 0; q < KPR; q++) {
        int kp = team * 32 + KPS + q;
        wr0[q] = W64[(size_t)kp * 512 + c0];
        wr1[q] = W64[(size_t)kp * 512 + c1];
    }
    for (int i = tid; i < 64 * HPS + ROWS * HH; i += 512) sh_hp[i] = 0.0f;
    __syncthreads();

    const u64* sW64 = (const u64*)sWp;
    const u64* tW = sW64 + (size_t)team * KPS * 512;
    const float* th = sh_hp + team * 32 * HPS;

    int ri[ROWS];
#pragma unroll
    for (int r = 0; r < ROWS; r++) {
        int g = b0 + r;
        ri[r] = (g < BB) ? g : (BB - 1);
    }

    int tok[ROWS];
    if (team == 0) {
        const int t0 = dir ? (LL - 1) : 0;
#pragma unroll
        for (int r = 0; r < ROWS; r++) tok[r] = sentences[ri[r] * LL + t0];
    }

    for (int s = 0; s < LL; s++) {
        const int t = dir ? (LL - 1 - s) : s;

        float xg0[ROWS], xg1[ROWS];
        if (team == 0) {
#pragma unroll
            for (int r = 0; r < ROWS; r++) {
                const float* base = xgv + (size_t)tok[r] * 1024 + dir * GATES;
                xg0[r] = base[c0];
                xg1[r] = base[c1];
            }
            if (s + 1 < LL) {
                const int tn = dir ? (LL - 2 - s) : (s + 1);
#pragma unroll
                for (int r = 0; r < ROWS; r++) tok[r] = sentences[ri[r] * LL + tn];
            }
        }

        u64 acc0[ROWS], acc1[ROWS];
#pragma unroll
        for (int r = 0; r < ROWS; r++) { acc0[r] = 0ull; acc1[r] = 0ull; }

#pragma unroll 3
        for (int p = 0; p < KPS; p++) {
            u64 w0 = tW[p * 512 + c0];
            u64 w1 = tW[p * 512 + c1];
            MM14(acc0, acc1, w0, w1, th + p * HPS);
        }
#pragma unroll
        for (int q = 0; q < KPR; q++) {
            MM14(acc0, acc1, wr0[q], wr1[q], th + (KPS + q) * HPS);
        }

        if (team == 0) {
#pragma unroll
            for (int r = 0; r < ROWS; r++) {
                float lo, hi;
                unpack2(acc0[r], lo, hi);
                sh_g[r * GATES + c0] = lo + hi + xg0[r];
                unpack2(acc1[r], lo, hi);
                sh_g[r * GATES + c1] = lo + hi + xg1[r];
            }
        } else {
#pragma unroll
            for (int r = 0; r < ROWS; r++) {
                float lo, hi;
                unpack2(acc0[r], lo, hi);
                sh_gp[r * GATES + c0] = lo + hi;
                unpack2(acc1[r], lo, hi);
                sh_gp[r * GATES + c1] = lo + hi;
            }
        }
        __syncthreads();

#pragma unroll
        for (int u = 0; u < 2; u++) {
            const int cell = u * 512 + tid;
            const int r = cell >> 7, k = cell & 127;
            if (r < ROWS) {
                const float gi = sh_g[r * GATES + k]          + sh_gp[r * GATES + k];
                const float gf = sh_g[r * GATES + HH + k]     + sh_gp[r * GATES + HH + k];
                const float gg = sh_g[r * GATES + 2 * HH + k] + sh_gp[r * GATES + 2 * HH + k];
                const float go = sh_g[r * GATES + 3 * HH + k] + sh_gp[r * GATES + 3 * HH + k];
                const float cn = sigm(gf) * sh_c[r * HH + k] + sigm(gi) * tanh_acc(gg);
                sh_c[r * HH + k] = cn;
                const float hn = sigm(go) * tanh_acc(cn);
                sh_hp[(k >> 1) * HPS + r * 2 + (k & 1)] = hn;
                if (b0 + r < BB)
                    hout[((size_t)(b0 + r) * LL + t) * DD + dir * HH + k] = hn;
            }
        }
        __syncthreads();
    }
}

// ---------------- tag projection ---------------------------------------------
__global__ void __launch_bounds__(256) tag_kernel(
    const float* __restrict__ h2, const float* __restrict__ Wt,
    const float* __restrict__ bt, float* __restrict__ logits)
{
    const int warp = threadIdx.x >> 5, lane = threadIdx.x & 31;
    const int m = blockIdx.x * 8 + warp;
    const float* row = h2 + (size_t)m * DD;
    float4 x0 = *(const float4*)(row + lane * 4);
    float4 x1 = *(const float4*)(row + 128 + lane * 4);
    float acc[TT];
#pragma unroll
    for (int t = 0; t < TT; t++) {
        const float* w = Wt + t * DD;
        float4 w0 = *(const float4*)(w + lane * 4);
        float4 w1 = *(const float4*)(w + 128 + lane * 4);
        float s = 0.0f;
        s = fmaf(x0.x, w0.x, s); s = fmaf(x0.y, w0.y, s);
        s = fmaf(x0.z, w0.z, s); s = fmaf(x0.w, w0.w, s);
        s = fmaf(x1.x, w1.x, s); s = fmaf(x1.y, w1.y, s);
        s = fmaf(x1.z, w1.z, s); s = fmaf(x1.w, w1.w, s);
        acc[t] = s;
    }
#pragma unroll
    for (int t = 0; t < TT; t++)
#pragma unroll
        for (int off = 16; off; off >>= 1)
            acc[t] += __shfl_xor_sync(0xFFFFFFFFu, acc[t], off);
    if (lane < TT) {
        float v = 0.0f;
#pragma unroll
        for (int t = 0; t < TT; t++) if (lane == t) v = acc[t];
        v = leaky(v + bt[lane]);
        logits[(size_t)m * TT + lane] = v;
    }
}

// ---------------- Viterbi -----------------------------------------------------
__global__ void __launch_bounds__(32) viterbi_kernel(
    const float* __restrict__ logits, const float* __restrict__ trans,
    float* __restrict__ out)
{
    const int b = blockIdx.x;
    const int j = threadIdx.x;
    __shared__ float tr[TT * TT];
    __shared__ float prev[8], cur[8];
    __shared__ unsigned char bp[LL][TT];
    if (j < TT * TT) tr[j] = trans[j];
    const float* lg = logits + (size_t)b * LL * TT;
    if (j < TT) prev[j] = lg[j];
    __syncwarp();
    for (int l = 1; l < LL; l++) {
        if (j < TT) {
            float best = prev[0] + tr[0 * TT + j];
            int arg = 0;
#pragma unroll
            for (int i = 1; i < TT; i++) {
                float v = prev[i] + tr[i * TT + j];
                if (v > best) { best = v; arg = i; }
            }
            cur[j] = lg[l * TT + j] + best;
            bp[l][j] = (unsigned char)arg;
        }
        __syncwarp();
        if (j < TT) prev[j] = cur[j];
        __syncwarp();
    }
    if (j == 0) {
        float best = prev[0]; int arg = 0;
#pragma unroll
        for (int i = 1; i < TT; i++)
            if (prev[i] > best) { best = prev[i]; arg = i; }
        out[b] = best;
        float* path = out + BB + (size_t)b * LL;
        int tag = arg;
        path[LL - 1] = (float)tag;
        for (int l = LL - 1; l >= 1; l--) {
            tag = bp[l][tag];
            path[l - 1] = (float)tag;
        }
    }
}

// ---------------- launch ------------------------------------------------------
extern "C" void kernel_launch(void* const* d_in, const int* in_sizes, int n_in,
                              void* d_out, int out_size)
{
    const int*   sentences = (const int*)d_in[0];
    const float* emb    = (const float*)d_in[2];
    const float* Wih_f  = (const float*)d_in[3];
    const float* Whh_f  = (const float*)d_in[4];
    const float* bih_f  = (const float*)d_in[5];
    const float* bhh_f  = (const float*)d_in[6];
    const float* Wih_b  = (const float*)d_in[7];
    const float* Whh_b  = (const float*)d_in[8];
    const float* bih_b  = (const float*)d_in[9];
    const float* bhh_b  = (const float*)d_in[10];
    const float* W1     = (const float*)d_in[11];
    const float* b1     = (const float*)d_in[12];
    const float* W2     = (const float*)d_in[13];
    const float* b2     = (const float*)d_in[14];
    const float* Wt     = (const float*)d_in[15];
    const float* bt     = (const float*)d_in[16];
    const float* trans  = (const float*)d_in[17];
    float* out = (float*)d_out;

    float *p_embW, *p_h, *p_h1, *p_h2, *p_logits, *p_Wf, *p_Wb;
    cudaGetSymbolAddress((void**)&p_embW,   g_embW);
    cudaGetSymbolAddress((void**)&p_h,      g_h);
    cudaGetSymbolAddress((void**)&p_h1,     g_h1);
    cudaGetSymbolAddress((void**)&p_h2,     g_h2);
    cudaGetSymbolAddress((void**)&p_logits, g_logits);
    cudaGetSymbolAddress((void**)&p_Wf,     g_Wpack_f);
    cudaGetSymbolAddress((void**)&p_Wb,     g_Wpack_b);

    const int lstm_smem =
        (2 * KPS * 1024 + 64 * HPS + ROWS * HH + 2 * ROWS * GATES) * 4;  // ~205 KB
    cudaFuncSetAttribute(lstm_kernel, cudaFuncAttributeMaxDynamicSharedMemorySize, lstm_smem);

    prep_kernel<<<256, 256>>>(Whh_f, Whh_b);

    gemmvocab<<<dim3(8, 391), 256>>>(
        emb, Wih_f, Wih_b, bih_f, bhh_f, bih_b, bhh_b, p_embW);

    lstm_kernel<<<2 * NGRP, 512, lstm_smem>>>(sentences, p_embW, p_Wf, p_Wb, p_h);

    gemm64n<1><<<dim3(4, MROWS / 128), 256>>>(
        p_h, W1, b1, p_h1, DD, DD, MROWS);
    gemm64n<1><<<dim3(4, MROWS / 128), 256>>>(
        p_h1, W2, b2, p_h2, DD, DD, MROWS);

    tag_kernel<<<MROWS / 8, 256>>>(p_h2, Wt, bt, p_logits);

    viterbi_kernel<<<BB, 32>>>(p_logits, trans, out);

    (void)in_sizes; (void)n_in; (void)out_size;
}

// round 17
// speedup vs baseline: 1.0622x; 1.0622x over previous
#include <cuda_runtime.h>
#include <cuda_bf16.h>
#include <math.h>

// Problem constants
#define BB   512
#define LL   200
#define EE   256
#define HH   128
#define DD   256
#define TT   6
#define GATES 512
#define MROWS (BB*LL)   // 102400
#define VV   50000
#define KPS  21         // Whh k-pairs per team cached in smem
#define KPR  11         // k-pairs per team in registers (KPS+KPR = 32)
#define ROWS 7          // batch rows per LSTM block (74 groups x 2 dirs = 148 blocks)
#define NGRP 74
#define HPS  20         // sh_hp stride per kp (floats): 16B-aligned, ~conflict-free scatter

typedef unsigned long long u64;

// ---------------- scratch -----------------------------------------------------
__device__ float g_embW[(size_t)50048 * 1024];   // per-vocab gate preactivations
__device__ float g_h [(size_t)MROWS * DD];
__device__ float g_h1[(size_t)MROWS * DD];
__device__ float g_h2[(size_t)MROWS * DD];
__device__ float g_logits[(size_t)MROWS * TT];
__device__ float g_Wpack_f[HH * GATES];   // [kp][j][parity] interleaved k-pairs
__device__ float g_Wpack_b[HH * GATES];

// ---------------- f32x2 helpers ----------------------------------------------
__device__ __forceinline__ u64 pack2(float lo, float hi) {
    u64 r; asm("mov.b64 %0, {%1, %2};" : "=l"(r) : "f"(lo), "f"(hi)); return r;
}
__device__ __forceinline__ void unpack2(u64 v, float& lo, float& hi) {
    asm("mov.b64 {%0, %1}, %2;" : "=f"(lo), "=f"(hi) : "l"(v));
}
__device__ __forceinline__ void ffma2(u64& d, u64 a, u64 b) {
    asm("fma.rn.f32x2 %0, %1, %2, %0;" : "+l"(d) : "l"(a), "l"(b));
}

__device__ __forceinline__ float sigm(float x) { return 1.0f / (1.0f + expf(-x)); }
__device__ __forceinline__ float tanh_acc(float x) {
    float e = expf(2.0f * x);
    return 1.0f - 2.0f / (e + 1.0f);
}
__device__ __forceinline__ float leaky(float x) { return (x >= 0.0f) ? x : 0.01f * x; }

// ---------------- prep: k-pair-pack Whh only ---------------------------------
__global__ void prep_kernel(const float* __restrict__ Whh_f, const float* __restrict__ Whh_b) {
    int i = blockIdx.x * 256 + threadIdx.x;          // covers 65536
    int j = i >> 7, k = i & 127;                     // source Whh[j][k]
    int dst = (k >> 1) * 1024 + j * 2 + (k & 1);     // [kp][j][parity]
    g_Wpack_f[dst] = Whh_f[i];
    g_Wpack_b[dst] = Whh_b[i];
}

// ---------------- 128x128 fp32 GEMM (R9-proven), C = act(A @ Bw^T + bias) ----
template<int ACT>
__global__ void __launch_bounds__(256, 2) gemm128(
    const float* __restrict__ A,
    const float* __restrict__ Bw, const float* __restrict__ bias,
    float* __restrict__ C, int N, int K, int Mmax)
{
    __shared__ float As[2][16][128];
    __shared__ float Bs[2][16][128];
    const int tid = threadIdx.x;
    const int mbase = blockIdx.y * 128;
    const int nbase = blockIdx.x * 128;
    const int lr = tid >> 1;           // 0..127
    const int lc = (tid & 1) << 3;     // 0 or 8
    int arow_i = mbase + lr;
    if (arow_i > Mmax - 1) arow_i = Mmax - 1;
    const float* arow = A + (size_t)arow_i * K;
    const float* brow = Bw + (size_t)(nbase + lr) * K;

    const int m0 = (tid >> 4) << 2;    // 4*mg
    const int n0 = (tid & 15) << 2;    // 4*ng

    u64 acc[4][8];
#pragma unroll
    for (int i = 0; i < 4; i++)
#pragma unroll
        for (int j = 0; j < 8; j++) acc[i][j] = 0ull;

    float4 a0 = *(const float4*)(arow + lc);
    float4 a1 = *(const float4*)(arow + lc + 4);
    float4 b0 = *(const float4*)(brow + lc);
    float4 b1 = *(const float4*)(brow + lc + 4);
    As[0][lc + 0][lr] = a0.x; As[0][lc + 1][lr] = a0.y;
    As[0][lc + 2][lr] = a0.z; As[0][lc + 3][lr] = a0.w;
    As[0][lc + 4][lr] = a1.x; As[0][lc + 5][lr] = a1.y;
    As[0][lc + 6][lr] = a1.z; As[0][lc + 7][lr] = a1.w;
    Bs[0][lc + 0][lr] = b0.x; Bs[0][lc + 1][lr] = b0.y;
    Bs[0][lc + 2][lr] = b0.z; Bs[0][lc + 3][lr] = b0.w;
    Bs[0][lc + 4][lr] = b1.x; Bs[0][lc + 5][lr] = b1.y;
    Bs[0][lc + 6][lr] = b1.z; Bs[0][lc + 7][lr] = b1.w;
    __syncthreads();

    int buf = 0;
    for (int kt = 0; kt < K; kt += 16) {
        const bool more = (kt + 16) < K;
        if (more) {
            a0 = *(const float4*)(arow + kt + 16 + lc);
            a1 = *(const float4*)(arow + kt + 16 + lc + 4);
            b0 = *(const float4*)(brow + kt + 16 + lc);
            b1 = *(const float4*)(brow + kt + 16 + lc + 4);
        }
#pragma unroll
        for (int kk = 0; kk < 16; kk++) {
            ulonglong2 av0 = *(const ulonglong2*)(&As[buf][kk][m0]);
            ulonglong2 av1 = *(const ulonglong2*)(&As[buf][kk][64 + m0]);
            float4 bv0 = *(const float4*)(&Bs[buf][kk][n0]);
            float4 bv1 = *(const float4*)(&Bs[buf][kk][64 + n0]);
            u64 bp[8];
            bp[0] = pack2(bv0.x, bv0.x); bp[1] = pack2(bv0.y, bv0.y);
            bp[2] = pack2(bv0.z, bv0.z); bp[3] = pack2(bv0.w, bv0.w);
            bp[4] = pack2(bv1.x, bv1.x); bp[5] = pack2(bv1.y, bv1.y);
            bp[6] = pack2(bv1.z, bv1.z); bp[7] = pack2(bv1.w, bv1.w);
            u64 am[4] = {av0.x, av0.y, av1.x, av1.y};
#pragma unroll
            for (int mp = 0; mp < 4; mp++)
#pragma unroll
                for (int n = 0; n < 8; n++)
                    ffma2(acc[mp][n], am[mp], bp[n]);
        }
        if (more) {
            const int nb = buf ^ 1;
            As[nb][lc + 0][lr] = a0.x; As[nb][lc + 1][lr] = a0.y;
            As[nb][lc + 2][lr] = a0.z; As[nb][lc + 3][lr] = a0.w;
            As[nb][lc + 4][lr] = a1.x; As[nb][lc + 5][lr] = a1.y;
            As[nb][lc + 6][lr] = a1.z; As[nb][lc + 7][lr] = a1.w;
            Bs[nb][lc + 0][lr] = b0.x; Bs[nb][lc + 1][lr] = b0.y;
            Bs[nb][lc + 2][lr] = b0.z; Bs[nb][lc + 3][lr] = b0.w;
            Bs[nb][lc + 4][lr] = b1.x; Bs[nb][lc + 5][lr] = b1.y;
            Bs[nb][lc + 6][lr] = b1.z; Bs[nb][lc + 7][lr] = b1.w;
            __syncthreads();
            buf = nb;
        }
    }

    float bsv[8];
#pragma unroll
    for (int n = 0; n < 4; n++) {
        bsv[n]     = bias[nbase + n0 + n];
        bsv[4 + n] = bias[nbase + 64 + n0 + n];
    }

#pragma unroll
    for (int mp = 0; mp < 4; mp++) {
        float r0[8], r1[8];
#pragma unroll
        for (int n = 0; n < 8; n++) unpack2(acc[mp][n], r0[n], r1[n]);
        const int row0 = mbase + m0 + (mp & 1) * 2 + (mp >> 1) * 64;
        const size_t base0 = (size_t)row0 * N;
        const size_t base1 = base0 + N;
        float4 v00, v01, v10, v11;
        float *p00 = (float*)&v00, *p01 = (float*)&v01;
        float *p10 = (float*)&v10, *p11 = (float*)&v11;
#pragma unroll
        for (int n = 0; n < 4; n++) {
            float x00 = r0[n] + bsv[n],     x01 = r0[4 + n] + bsv[4 + n];
            float x10 = r1[n] + bsv[n],     x11 = r1[4 + n] + bsv[4 + n];
            if (ACT) { x00 = leaky(x00); x01 = leaky(x01); x10 = leaky(x10); x11 = leaky(x11); }
            p00[n] = x00; p01[n] = x01; p10[n] = x10; p11[n] = x11;
        }
        *(float4*)(&C[base0 + nbase + n0])      = v00;
        *(float4*)(&C[base0 + nbase + 64 + n0]) = v01;
        *(float4*)(&C[base1 + nbase + n0])      = v10;
        *(float4*)(&C[base1 + nbase + 64 + n0]) = v11;
    }
}

// ---------------- vocab GEMM: embW = emb @ [Wih_f;Wih_b]^T + (bih+bhh) -------
__global__ void __launch_bounds__(256, 2) gemmvocab(
    const float* __restrict__ A,
    const float* __restrict__ Wf, const float* __restrict__ Wb,
    const float* __restrict__ bihf, const float* __restrict__ bhhf,
    const float* __restrict__ bihb, const float* __restrict__ bhhb,
    float* __restrict__ C)
{
    const int N = 1024, K = EE;
    __shared__ float As[2][16][128];
    __shared__ float Bs[2][16][128];
    const int tid = threadIdx.x;
    const int mbase = blockIdx.y * 128;
    const int nbase = blockIdx.x * 128;
    const int lr = tid >> 1;
    const int lc = (tid & 1) << 3;
    int arow_i = mbase + lr;
    if (arow_i > VV - 1) arow_i = VV - 1;
    const float* arow = A + (size_t)arow_i * K;
    const int bri = nbase + lr;
    const float* brow = (bri < 512) ? (Wf + (size_t)bri * K)
                                    : (Wb + (size_t)(bri - 512) * K);

    const int m0 = (tid >> 4) << 2;
    const int n0 = (tid & 15) << 2;

    u64 acc[4][8];
#pragma unroll
    for (int i = 0; i < 4; i++)
#pragma unroll
        for (int j = 0; j < 8; j++) acc[i][j] = 0ull;

    float4 a0 = *(const float4*)(arow + lc);
    float4 a1 = *(const float4*)(arow + lc + 4);
    float4 b0 = *(const float4*)(brow + lc);
    float4 b1 = *(const float4*)(brow + lc + 4);
    As[0][lc + 0][lr] = a0.x; As[0][lc + 1][lr] = a0.y;
    As[0][lc + 2][lr] = a0.z; As[0][lc + 3][lr] = a0.w;
    As[0][lc + 4][lr] = a1.x; As[0][lc + 5][lr] = a1.y;
    As[0][lc + 6][lr] = a1.z; As[0][lc + 7][lr] = a1.w;
    Bs[0][lc + 0][lr] = b0.x; Bs[0][lc + 1][lr] = b0.y;
    Bs[0][lc + 2][lr] = b0.z; Bs[0][lc + 3][lr] = b0.w;
    Bs[0][lc + 4][lr] = b1.x; Bs[0][lc + 5][lr] = b1.y;
    Bs[0][lc + 6][lr] = b1.z; Bs[0][lc + 7][lr] = b1.w;
    __syncthreads();

    int buf = 0;
    for (int kt = 0; kt < K; kt += 16) {
        const bool more = (kt + 16) < K;
        if (more) {
            a0 = *(const float4*)(arow + kt + 16 + lc);
            a1 = *(const float4*)(arow + kt + 16 + lc + 4);
            b0 = *(const float4*)(brow + kt + 16 + lc);
            b1 = *(const float4*)(brow + kt + 16 + lc + 4);
        }
#pragma unroll
        for (int kk = 0; kk < 16; kk++) {
            ulonglong2 av0 = *(const ulonglong2*)(&As[buf][kk][m0]);
            ulonglong2 av1 = *(const ulonglong2*)(&As[buf][kk][64 + m0]);
            float4 bv0 = *(const float4*)(&Bs[buf][kk][n0]);
            float4 bv1 = *(const float4*)(&Bs[buf][kk][64 + n0]);
            u64 bp[8];
            bp[0] = pack2(bv0.x, bv0.x); bp[1] = pack2(bv0.y, bv0.y);
            bp[2] = pack2(bv0.z, bv0.z); bp[3] = pack2(bv0.w, bv0.w);
            bp[4] = pack2(bv1.x, bv1.x); bp[5] = pack2(bv1.y, bv1.y);
            bp[6] = pack2(bv1.z, bv1.z); bp[7] = pack2(bv1.w, bv1.w);
            u64 am[4] = {av0.x, av0.y, av1.x, av1.y};
#pragma unroll
            for (int mp = 0; mp < 4; mp++)
#pragma unroll
                for (int n = 0; n < 8; n++)
                    ffma2(acc[mp][n], am[mp], bp[n]);
        }
        if (more) {
            const int nb = buf ^ 1;
            As[nb][lc + 0][lr] = a0.x; As[nb][lc + 1][lr] = a0.y;
            As[nb][lc + 2][lr] = a0.z; As[nb][lc + 3][lr] = a0.w;
            As[nb][lc + 4][lr] = a1.x; As[nb][lc + 5][lr] = a1.y;
            As[nb][lc + 6][lr] = a1.z; As[nb][lc + 7][lr] = a1.w;
            Bs[nb][lc + 0][lr] = b0.x; Bs[nb][lc + 1][lr] = b0.y;
            Bs[nb][lc + 2][lr] = b0.z; Bs[nb][lc + 3][lr] = b0.w;
            Bs[nb][lc + 4][lr] = b1.x; Bs[nb][lc + 5][lr] = b1.y;
            Bs[nb][lc + 6][lr] = b1.z; Bs[nb][lc + 7][lr] = b1.w;
            __syncthreads();
            buf = nb;
        }
    }

    float bsv[8];
#pragma unroll
    for (int n = 0; n < 8; n++) {
        const int col = nbase + ((n < 4) ? n0 + n : 64 + n0 + (n - 4));
        bsv[n] = (col < 512) ? (bihf[col] + bhhf[col])
                             : (bihb[col - 512] + bhhb[col - 512]);
    }

#pragma unroll
    for (int mp = 0; mp < 4; mp++) {
        float r0[8], r1[8];
#pragma unroll
        for (int n = 0; n < 8; n++) unpack2(acc[mp][n], r0[n], r1[n]);
        const int row0 = mbase + m0 + (mp & 1) * 2 + (mp >> 1) * 64;
        const size_t base0 = (size_t)row0 * N;
        const size_t base1 = base0 + N;
        float4 v00, v01, v10, v11;
        float *p00 = (float*)&v00, *p01 = (float*)&v01;
        float *p10 = (float*)&v10, *p11 = (float*)&v11;
#pragma unroll
        for (int n = 0; n < 4; n++) {
            p00[n] = r0[n] + bsv[n];     p01[n] = r0[4 + n] + bsv[4 + n];
            p10[n] = r1[n] + bsv[n];     p11[n] = r1[4 + n] + bsv[4 + n];
        }
        *(float4*)(&C[base0 + nbase + n0])      = v00;
        *(float4*)(&C[base0 + nbase + 64 + n0]) = v01;
        *(float4*)(&C[base1 + nbase + n0])      = v10;
        *(float4*)(&C[base1 + nbase + 64 + n0]) = v11;
    }
}

// ---------------- persistent BiLSTM: split-k, paired columns {2tt,2tt+1} -----
// Wide accesses: W via LDS.128, xg via LDG.64, gate partials via STS.64.
#define MM14(ACA, ACB, W0, W1, HPTR)                                      \
    {                                                                     \
        const ulonglong2* hp_ = (const ulonglong2*)(HPTR);                \
        ulonglong2 hA = hp_[0], hB = hp_[1], hC = hp_[2];                 \
        u64 h6 = *(const u64*)(((const float*)(HPTR)) + 12);              \
        ffma2(ACA[0], hA.x, W0); ffma2(ACB[0], hA.x, W1);                 \
        ffma2(ACA[1], hA.y, W0); ffma2(ACB[1], hA.y, W1);                 \
        ffma2(ACA[2], hB.x, W0); ffma2(ACB[2], hB.x, W1);                 \
        ffma2(ACA[3], hB.y, W0); ffma2(ACB[3], hB.y, W1);                 \
        ffma2(ACA[4], hC.x, W0); ffma2(ACB[4], hC.x, W1);                 \
        ffma2(ACA[5], hC.y, W0); ffma2(ACB[5], hC.y, W1);                 \
        ffma2(ACA[6], h6,   W0); ffma2(ACB[6], h6,   W1);                 \
    }

__global__ void __launch_bounds__(512) lstm_kernel(
    const int* __restrict__ sentences,
    const float* __restrict__ xgv,
    const float* __restrict__ Wp_f, const float* __restrict__ Wp_b,
    float* __restrict__ hout)
{
    extern __shared__ float dyn[];
    float* sWp   = dyn;                           // [2 teams][KPS][512][2]
    float* sh_hp = dyn + 2 * KPS * 1024;          // [64 kp][HPS]
    float* sh_c  = sh_hp + 64 * HPS;              // [7][128]
    float* sh_g  = sh_c + ROWS * HH;              // [7][512] team0 partial + xg
    float* sh_gp = sh_g + ROWS * GATES;           // [7][512] team1 partial

    const int tid = threadIdx.x;
    const int team = tid >> 8;
    const int tt = tid & 255;
    const int c0 = tt << 1;            // paired adjacent gate columns
    const int dir = blockIdx.x & 1;
    const int b0 = (blockIdx.x >> 1) * ROWS;
    const float* __restrict__ W = dir ? Wp_b : Wp_f;
    const u64* __restrict__ W64 = (const u64*)W;

    for (int i = tid; i < 2 * KPS * 1024; i += 512) {
        int slot = i >> 10, c = i & 1023;
        int m = slot / KPS, p = slot - m * KPS;
        sWp[i] = W[((m * 32 + p) << 10) + c];
    }
    u64 wr0[KPR], wr1[KPR];
#pragma unroll
    for (int q = 0; q < KPR; q++) {
        int kp = team * 32 + KPS + q;
        ulonglong2 wv = *(const ulonglong2*)(W64 + (size_t)kp * 512 + c0);
        wr0[q] = wv.x;
        wr1[q] = wv.y;
    }
    for (int i = tid; i < 64 * HPS + ROWS * HH; i += 512) sh_hp[i] = 0.0f;
    __syncthreads();

    const u64* sW64 = (const u64*)sWp;
    const u64* tW = sW64 + (size_t)team * KPS * 512;
    const float* th = sh_hp + team * 32 * HPS;

    int ri[ROWS];
#pragma unroll
    for (int r = 0; r < ROWS; r++) {
        int g = b0 + r;
        ri[r] = (g < BB) ? g : (BB - 1);
    }

    int tok[ROWS];
    if (team == 0) {
        const int t0 = dir ? (LL - 1) : 0;
#pragma unroll
        for (int r = 0; r < ROWS; r++) tok[r] = sentences[ri[r] * LL + t0];
    }

    for (int s = 0; s < LL; s++) {
        const int t = dir ? (LL - 1 - s) : s;

        // xg gather: one LDG.64 per row (adjacent columns), overlaps matvec
        float2 xg2[ROWS];
        if (team == 0) {
#pragma unroll
            for (int r = 0; r < ROWS; r++)
                xg2[r] = *(const float2*)(xgv + (size_t)tok[r] * 1024 + dir * GATES + c0);
            if (s + 1 < LL) {
                const int tn = dir ? (LL - 2 - s) : (s + 1);
#pragma unroll
                for (int r = 0; r < ROWS; r++) tok[r] = sentences[ri[r] * LL + tn];
            }
        }

        u64 acc0[ROWS], acc1[ROWS];
#pragma unroll
        for (int r = 0; r < ROWS; r++) { acc0[r] = 0ull; acc1[r] = 0ull; }

#pragma unroll 3
        for (int p = 0; p < KPS; p++) {
            ulonglong2 wv = *(const ulonglong2*)(tW + p * 512 + c0);  // LDS.128
            MM14(acc0, acc1, wv.x, wv.y, th + p * HPS);
        }
#pragma unroll
        for (int q = 0; q < KPR; q++) {
            MM14(acc0, acc1, wr0[q], wr1[q], th + (KPS + q) * HPS);
        }

        if (team == 0) {
#pragma unroll
            for (int r = 0; r < ROWS; r++) {
                float lo0, hi0, lo1, hi1;
                unpack2(acc0[r], lo0, hi0);
                unpack2(acc1[r], lo1, hi1);
                float2 v = make_float2(lo0 + hi0 + xg2[r].x, lo1 + hi1 + xg2[r].y);
                *(float2*)(&sh_g[r * GATES + c0]) = v;               // STS.64
            }
        } else {
#pragma unroll
            for (int r = 0; r < ROWS; r++) {
                float lo0, hi0, lo1, hi1;
                unpack2(acc0[r], lo0, hi0);
                unpack2(acc1[r], lo1, hi1);
                float2 v = make_float2(lo0 + hi0, lo1 + hi1);
                *(float2*)(&sh_gp[r * GATES + c0]) = v;              // STS.64
            }
        }
        __syncthreads();

#pragma unroll
        for (int u = 0; u < 2; u++) {
            const int cell = u * 512 + tid;
            const int r = cell >> 7, k = cell & 127;
            if (r < ROWS) {
                const float gi = sh_g[r * GATES + k]          + sh_gp[r * GATES + k];
                const float gf = sh_g[r * GATES + HH + k]     + sh_gp[r * GATES + HH + k];
                const float gg = sh_g[r * GATES + 2 * HH + k] + sh_gp[r * GATES + 2 * HH + k];
                const float go = sh_g[r * GATES + 3 * HH + k] + sh_gp[r * GATES + 3 * HH + k];
                const float cn = sigm(gf) * sh_c[r * HH + k] + sigm(gi) * tanh_acc(gg);
                sh_c[r * HH + k] = cn;
                const float hn = sigm(go) * tanh_acc(cn);
                sh_hp[(k >> 1) * HPS + r * 2 + (k & 1)] = hn;
                if (b0 + r < BB)
                    hout[((size_t)(b0 + r) * LL + t) * DD + dir * HH + k] = hn;
            }
        }
        __syncthreads();
    }
}

// ---------------- tag projection ---------------------------------------------
__global__ void __launch_bounds__(256) tag_kernel(
    const float* __restrict__ h2, const float* __restrict__ Wt,
    const float* __restrict__ bt, float* __restrict__ logits)
{
    const int warp = threadIdx.x >> 5, lane = threadIdx.x & 31;
    const int m = blockIdx.x * 8 + warp;
    const float* row = h2 + (size_t)m * DD;
    float4 x0 = *(const float4*)(row + lane * 4);
    float4 x1 = *(const float4*)(row + 128 + lane * 4);
    float acc[TT];
#pragma unroll
    for (int t = 0; t < TT; t++) {
        const float* w = Wt + t * DD;
        float4 w0 = *(const float4*)(w + lane * 4);
        float4 w1 = *(const float4*)(w + 128 + lane * 4);
        float s = 0.0f;
        s = fmaf(x0.x, w0.x, s); s = fmaf(x0.y, w0.y, s);
        s = fmaf(x0.z, w0.z, s); s = fmaf(x0.w, w0.w, s);
        s = fmaf(x1.x, w1.x, s); s = fmaf(x1.y, w1.y, s);
        s = fmaf(x1.z, w1.z, s); s = fmaf(x1.w, w1.w, s);
        acc[t] = s;
    }
#pragma unroll
    for (int t = 0; t < TT; t++)
#pragma unroll
        for (int off = 16; off; off >>= 1)
            acc[t] += __shfl_xor_sync(0xFFFFFFFFu, acc[t], off);
    if (lane < TT) {
        float v = 0.0f;
#pragma unroll
        for (int t = 0; t < TT; t++) if (lane == t) v = acc[t];
        v = leaky(v + bt[lane]);
        logits[(size_t)m * TT + lane] = v;
    }
}

// ---------------- Viterbi -----------------------------------------------------
__global__ void __launch_bounds__(32) viterbi_kernel(
    const float* __restrict__ logits, const float* __restrict__ trans,
    float* __restrict__ out)
{
    const int b = blockIdx.x;
    const int j = threadIdx.x;
    __shared__ float tr[TT * TT];
    __shared__ float prev[8], cur[8];
    __shared__ unsigned char bp[LL][TT];
    if (j < TT * TT) tr[j] = trans[j];
    const float* lg = logits + (size_t)b * LL * TT;
    if (j < TT) prev[j] = lg[j];
    __syncwarp();
    for (int l = 1; l < LL; l++) {
        if (j < TT) {
            float best = prev[0] + tr[0 * TT + j];
            int arg = 0;
#pragma unroll
            for (int i = 1; i < TT; i++) {
                float v = prev[i] + tr[i * TT + j];
                if (v > best) { best = v; arg = i; }
            }
            cur[j] = lg[l * TT + j] + best;
            bp[l][j] = (unsigned char)arg;
        }
        __syncwarp();
        if (j < TT) prev[j] = cur[j];
        __syncwarp();
    }
    if (j == 0) {
        float best = prev[0]; int arg = 0;
#pragma unroll
        for (int i = 1; i < TT; i++)
            if (prev[i] > best) { best = prev[i]; arg = i; }
        out[b] = best;
        float* path = out + BB + (size_t)b * LL;
        int tag = arg;
        path[LL - 1] = (float)tag;
        for (int l = LL - 1; l >= 1; l--) {
            tag = bp[l][tag];
            path[l - 1] = (float)tag;
        }
    }
}

// ---------------- launch ------------------------------------------------------
extern "C" void kernel_launch(void* const* d_in, const int* in_sizes, int n_in,
                              void* d_out, int out_size)
{
    const int*   sentences = (const int*)d_in[0];
    const float* emb    = (const float*)d_in[2];
    const float* Wih_f  = (const float*)d_in[3];
    const float* Whh_f  = (const float*)d_in[4];
    const float* bih_f  = (const float*)d_in[5];
    const float* bhh_f  = (const float*)d_in[6];
    const float* Wih_b  = (const float*)d_in[7];
    const float* Whh_b  = (const float*)d_in[8];
    const float* bih_b  = (const float*)d_in[9];
    const float* bhh_b  = (const float*)d_in[10];
    const float* W1     = (const float*)d_in[11];
    const float* b1     = (const float*)d_in[12];
    const float* W2     = (const float*)d_in[13];
    const float* b2     = (const float*)d_in[14];
    const float* Wt     = (const float*)d_in[15];
    const float* bt     = (const float*)d_in[16];
    const float* trans  = (const float*)d_in[17];
    float* out = (float*)d_out;

    float *p_embW, *p_h, *p_h1, *p_h2, *p_logits, *p_Wf, *p_Wb;
    cudaGetSymbolAddress((void**)&p_embW,   g_embW);
    cudaGetSymbolAddress((void**)&p_h,      g_h);
    cudaGetSymbolAddress((void**)&p_h1,     g_h1);
    cudaGetSymbolAddress((void**)&p_h2,     g_h2);
    cudaGetSymbolAddress((void**)&p_logits, g_logits);
    cudaGetSymbolAddress((void**)&p_Wf,     g_Wpack_f);
    cudaGetSymbolAddress((void**)&p_Wb,     g_Wpack_b);

    const int lstm_smem =
        (2 * KPS * 1024 + 64 * HPS + ROWS * HH + 2 * ROWS * GATES) * 4;  // ~205 KB
    cudaFuncSetAttribute(lstm_kernel, cudaFuncAttributeMaxDynamicSharedMemorySize, lstm_smem);

    prep_kernel<<<256, 256>>>(Whh_f, Whh_b);

    gemmvocab<<<dim3(8, 391), 256>>>(
        emb, Wih_f, Wih_b, bih_f, bhh_f, bih_b, bhh_b, p_embW);

    lstm_kernel<<<2 * NGRP, 512, lstm_smem>>>(sentences, p_embW, p_Wf, p_Wb, p_h);

    gemm128<1><<<dim3(2, MROWS / 128), 256>>>(
        p_h, W1, b1, p_h1, DD, DD, MROWS);
    gemm128<1><<<dim3(2, MROWS / 128), 256>>>(
        p_h1, W2, b2, p_h2, DD, DD, MROWS);

    tag_kernel<<<MROWS / 8, 256>>>(p_h2, Wt, bt, p_logits);

    viterbi_kernel<<<BB, 32>>>(p_logits, trans, out);

    (void)in_sizes; (void)n_in; (void)out_size;
}